// round 6
// baseline (speedup 1.0000x reference)
#include <cuda_runtime.h>
#include <cuda_bf16.h>
#include <cstdint>

// ---------------- problem constants ----------------
#define NROWS  10000
#define MPAD   10240           // 80 * 128 (divisible by 256)
#define NHID   128
#define NFEAT  512
#define KPAD   10048           // 157 * 64
#define BKC    64
#define NCHUNK (KPAD / BKC)    // 157

// ---------------- scratch (__device__ globals; no allocs) ----------------
__device__ __align__(256) float g_T1[NROWS * NHID];
__device__ __align__(256) float g_H [NROWS * NHID];
__device__ __align__(256) float g_T2[NROWS * NFEAT];
__device__ __align__(256) float g_part[4 * (size_t)MPAD * NFEAT];   // split-K partials
__device__ __align__(256) __nv_bfloat16 g_adj_hi[(size_t)MPAD * KPAD];
__device__ __align__(256) __nv_bfloat16 g_adj_lo[(size_t)MPAD * KPAD];
__device__ __align__(256) __nv_bfloat16 g_T1t_hi[NHID * KPAD];
__device__ __align__(256) __nv_bfloat16 g_T1t_lo[NHID * KPAD];
__device__ __align__(256) __nv_bfloat16 g_T2t_hi[NFEAT * KPAD];
__device__ __align__(256) __nv_bfloat16 g_T2t_lo[NFEAT * KPAD];

// ---------------- PTX helpers (legal on bare sm_103) ----------------
__device__ __forceinline__ uint32_t smem_u32(const void* p) {
    uint32_t a;
    asm("{ .reg .u64 t; cvta.to.shared.u64 t, %1; cvt.u32.u64 %0, t; }" : "=r"(a) : "l"(p));
    return a;
}
__device__ __forceinline__ uint32_t swz(uint32_t off) {
    return off ^ ((off >> 3) & 0x70);
}
__device__ __forceinline__ void cp_async16(uint32_t dst, const void* src) {
    asm volatile("cp.async.cg.shared.global [%0], [%1], 16;" :: "r"(dst), "l"(src));
}
__device__ __forceinline__ void cp_commit() {
    asm volatile("cp.async.commit_group;" ::: "memory");
}
template <int N>
__device__ __forceinline__ void cp_wait() {
    asm volatile("cp.async.wait_group %0;" :: "n"(N) : "memory");
}
__device__ __forceinline__ void ldsm4(uint32_t* r, uint32_t addr) {
    asm volatile("ldmatrix.sync.aligned.m8n8.x4.shared.b16 {%0,%1,%2,%3}, [%4];"
                 : "=r"(r[0]), "=r"(r[1]), "=r"(r[2]), "=r"(r[3]) : "r"(addr));
}
__device__ __forceinline__ void mma_bf16(float* d, const uint32_t* a,
                                         uint32_t b0, uint32_t b1) {
    asm volatile(
        "mma.sync.aligned.m16n8k16.row.col.f32.bf16.bf16.f32 "
        "{%0,%1,%2,%3}, {%4,%5,%6,%7}, {%8,%9}, {%0,%1,%2,%3};"
        : "+f"(d[0]), "+f"(d[1]), "+f"(d[2]), "+f"(d[3])
        : "r"(a[0]), "r"(a[1]), "r"(a[2]), "r"(a[3]), "r"(b0), "r"(b1));
}

// ---------------- HMMA split-bf16 GEMM (partial sums) ----------------
// Warp tile 32x64; CTA tile (WGM*32) x (WGN*64); 16 warps (WGM*WGN == 16).
// part[z][m][n] = sum_{k in z's range} (Ahi+Alo)[m][k]*(Bhi+Blo)[n][k]   (3 products)
// A: [MPAD, KPAD] bf16 K-major; B: [Ntot, KPAD] bf16 K-major.
template <int WGM, int WGN>
__global__ __launch_bounds__(512, 1)
void tc_gemm(const __nv_bfloat16* __restrict__ Ahi,
             const __nv_bfloat16* __restrict__ Alo,
             const __nv_bfloat16* __restrict__ Bhi,
             const __nv_bfloat16* __restrict__ Blo,
             float* __restrict__ C, int ldC, size_t part_stride)
{
    constexpr int BM  = WGM * 32;
    constexpr int BN  = WGN * 64;
    constexpr uint32_t A_B = (uint32_t)BM * 128u;   // one A tile bytes
    constexpr uint32_t B_B = (uint32_t)BN * 128u;   // one B tile bytes
    constexpr uint32_t SS  = 2u * A_B + 2u * B_B;   // stage bytes (= 98304 both cfgs)

    extern __shared__ __align__(128) char smem[];
    const uint32_t sbase = smem_u32(smem);
    const int tid  = threadIdx.x;
    const int wid  = tid >> 5;
    const int lane = tid & 31;
    const int wm = wid / WGN;
    const int wn = wid % WGN;
    const int m0 = blockIdx.y * BM;
    const int n0 = blockIdx.x * BN;

    const int gz = gridDim.z, bz = blockIdx.z;
    const int cbeg = (NCHUNK * bz) / gz;
    const int cend = (NCHUNK * (bz + 1)) / gz;
    C += (size_t)bz * part_stride;

    const char* baseAhi = (const char*)(Ahi + (size_t)m0 * KPAD);
    const char* baseAlo = (const char*)(Alo + (size_t)m0 * KPAD);
    const char* baseBhi = (const char*)(Bhi + (size_t)n0 * KPAD);
    const char* baseBlo = (const char*)(Blo + (size_t)n0 * KPAD);

    auto load_stage = [&](int c) {
        const uint32_t st = sbase + (uint32_t)(c & 1) * SS;
        const size_t kb = (size_t)c * 128;   // bytes along K
#pragma unroll
        for (int i = 0; i < 12; i++) {
            const int idx = tid + i * 512;   // 0..6143
            const int row = idx >> 3;
            const int cc  = idx & 7;
            const char* src;
            uint32_t dst;
            if (row < BM) {
                src = baseAhi + (size_t)row * (KPAD * 2) + kb + cc * 16;
                dst = st + swz((uint32_t)(row * 128 + cc * 16));
            } else if (row < 2 * BM) {
                const int r = row - BM;
                src = baseAlo + (size_t)r * (KPAD * 2) + kb + cc * 16;
                dst = st + A_B + swz((uint32_t)(r * 128 + cc * 16));
            } else if (row < 2 * BM + BN) {
                const int r = row - 2 * BM;
                src = baseBhi + (size_t)r * (KPAD * 2) + kb + cc * 16;
                dst = st + 2u * A_B + swz((uint32_t)(r * 128 + cc * 16));
            } else {
                const int r = row - 2 * BM - BN;
                src = baseBlo + (size_t)r * (KPAD * 2) + kb + cc * 16;
                dst = st + 2u * A_B + B_B + swz((uint32_t)(r * 128 + cc * 16));
            }
            cp_async16(dst, src);
        }
        cp_commit();
    };

    // ldmatrix logical offsets
    const uint32_t rL   = lane & 15;
    const uint32_t cAdd = (lane >> 4) * 16u;
    const uint32_t aRow0 = (uint32_t)(wm * 32) + rL;
    const uint32_t bRow0 = (uint32_t)(wn * 64) + rL;

    float acc[2][8][4];
#pragma unroll
    for (int i = 0; i < 2; i++)
#pragma unroll
        for (int j = 0; j < 8; j++)
#pragma unroll
            for (int k = 0; k < 4; k++) acc[i][j][k] = 0.0f;

    load_stage(cbeg);

    for (int c = cbeg; c < cend; c++) {
        __syncthreads();                       // stage (c+1)&1 free
        if (c + 1 < cend) { load_stage(c + 1); cp_wait<1>(); }
        else              { cp_wait<0>(); }
        __syncthreads();                       // c's data visible

        const uint32_t st   = sbase + (uint32_t)(c & 1) * SS;
        const uint32_t tAhi = st;
        const uint32_t tAlo = st + A_B;
        const uint32_t tBhi = st + 2u * A_B;
        const uint32_t tBlo = tBhi + B_B;

#pragma unroll
        for (int ks = 0; ks < 4; ks++) {
            const uint32_t kb = cAdd + (uint32_t)ks * 32u;
            uint32_t Ah[2][4], Al[2][4];
#pragma unroll
            for (int mt = 0; mt < 2; mt++) {
                const uint32_t off = (aRow0 + mt * 16u) * 128u + kb;
                ldsm4(Ah[mt], tAhi + swz(off));
                ldsm4(Al[mt], tAlo + swz(off));
            }
#pragma unroll
            for (int nh = 0; nh < 4; nh++) {
                const uint32_t off = (bRow0 + nh * 16u) * 128u + kb;
                uint32_t Bh[4], Bl[4];
                ldsm4(Bh, tBhi + swz(off));
                ldsm4(Bl, tBlo + swz(off));
#pragma unroll
                for (int mt = 0; mt < 2; mt++) {
                    float* a0 = acc[mt][2 * nh + 0];
                    float* a1 = acc[mt][2 * nh + 1];
                    mma_bf16(a0, Ah[mt], Bh[0], Bh[2]);   // hi*hi
                    mma_bf16(a1, Ah[mt], Bh[1], Bh[3]);
                    mma_bf16(a0, Ah[mt], Bl[0], Bl[2]);   // hi*lo
                    mma_bf16(a1, Ah[mt], Bl[1], Bl[3]);
                    mma_bf16(a0, Al[mt], Bh[0], Bh[2]);   // lo*hi
                    mma_bf16(a1, Al[mt], Bh[1], Bh[3]);
                }
            }
        }
    }

    // ---- epilogue: raw partial sums (buffers padded; no guards) ----
    const int trow  = lane >> 2;
    const int tcol2 = (lane & 3) * 2;
#pragma unroll
    for (int mt = 0; mt < 2; mt++) {
#pragma unroll
        for (int h = 0; h < 2; h++) {
            const int gr = m0 + wm * 32 + mt * 16 + h * 8 + trow;
#pragma unroll
            for (int nf = 0; nf < 8; nf++) {
                const int gc = n0 + wn * 64 + nf * 8 + tcol2;
                float2 v;
                v.x = acc[mt][nf][h * 2 + 0];
                v.y = acc[mt][nf][h * 2 + 1];
                *reinterpret_cast<float2*>(&C[(size_t)gr * ldC + gc]) = v;
            }
        }
    }
}

// ---------------- split-K reduce: out = (sum parts) + bias (, relu) ----------------
template <int NP, bool RELU>
__global__ void reduce_kernel(const float* __restrict__ part, size_t stride,
                              const float* __restrict__ bias,
                              float* __restrict__ out, int rows, int cols)
{
    const int t = blockIdx.x * blockDim.x + threadIdx.x;
    if (t >= rows * (cols / 4)) return;
    const int r = t / (cols / 4);
    const int c = (t % (cols / 4)) * 4;
    float4 s = *reinterpret_cast<const float4*>(bias + c);
#pragma unroll
    for (int p = 0; p < NP; p++) {
        const float4 v = *reinterpret_cast<const float4*>(part + p * stride + (size_t)r * cols + c);
        s.x += v.x; s.y += v.y; s.z += v.z; s.w += v.w;
    }
    if (RELU) {
        s.x = fmaxf(s.x, 0.0f); s.y = fmaxf(s.y, 0.0f);
        s.z = fmaxf(s.z, 0.0f); s.w = fmaxf(s.w, 0.0f);
    }
    *reinterpret_cast<float4*>(out + (size_t)r * cols + c) = s;
}

// ---------------- adj split: fp32 -> bf16 hi/lo [MPAD,KPAD] ----------------
__global__ void split_adj_kernel(const float* __restrict__ adj,
                                 __nv_bfloat16* __restrict__ hi,
                                 __nv_bfloat16* __restrict__ lo)
{
    const long long t = (long long)blockIdx.x * blockDim.x + threadIdx.x;
    const long long total = (long long)MPAD * (KPAD / 4);
    if (t >= total) return;
    const int c4 = (int)(t % (KPAD / 4));
    const int r  = (int)(t / (KPAD / 4));
    const int k  = c4 * 4;
    float4 v = make_float4(0.f, 0.f, 0.f, 0.f);
    if (r < NROWS && k < NROWS)
        v = *reinterpret_cast<const float4*>(adj + (size_t)r * NROWS + k);
    __nv_bfloat16 h0 = __float2bfloat16(v.x), h1 = __float2bfloat16(v.y);
    __nv_bfloat16 h2 = __float2bfloat16(v.z), h3 = __float2bfloat16(v.w);
    __nv_bfloat16 l0 = __float2bfloat16(v.x - __bfloat162float(h0));
    __nv_bfloat16 l1 = __float2bfloat16(v.y - __bfloat162float(h1));
    __nv_bfloat16 l2 = __float2bfloat16(v.z - __bfloat162float(h2));
    __nv_bfloat16 l3 = __float2bfloat16(v.w - __bfloat162float(h3));
    __nv_bfloat162 H01, H23, L01, L23;
    H01.x = h0; H01.y = h1; H23.x = h2; H23.y = h3;
    L01.x = l0; L01.y = l1; L23.x = l2; L23.y = l3;
    __nv_bfloat162* hp = reinterpret_cast<__nv_bfloat162*>(hi + (size_t)r * KPAD + k);
    __nv_bfloat162* lp = reinterpret_cast<__nv_bfloat162*>(lo + (size_t)r * KPAD + k);
    hp[0] = H01; hp[1] = H23;
    lp[0] = L01; lp[1] = L23;
}

// -------- tiled transpose + split: fp32 [R,C] -> bf16 hi/lo [C, KPAD] --------
// grid (C/32, KPAD/32), block (32, 8). Coalesced on both sides.
__global__ void tsplit_kernel(const float* __restrict__ in, int R, int C,
                              __nv_bfloat16* __restrict__ hi,
                              __nv_bfloat16* __restrict__ lo)
{
    __shared__ float tile[32][33];
    const int tx = threadIdx.x, ty = threadIdx.y;
    const int c0 = blockIdx.x * 32;
    const int k0 = blockIdx.y * 32;
#pragma unroll
    for (int i = 0; i < 4; i++) {
        const int k = k0 + ty + i * 8;
        tile[ty + i * 8][tx] = (k < R) ? in[(size_t)k * C + (c0 + tx)] : 0.0f;
    }
    __syncthreads();
#pragma unroll
    for (int i = 0; i < 4; i++) {
        const int c = c0 + ty + i * 8;
        const float v = tile[tx][ty + i * 8];
        const __nv_bfloat16 h = __float2bfloat16(v);
        hi[(size_t)c * KPAD + k0 + tx] = h;
        lo[(size_t)c * KPAD + k0 + tx] = __float2bfloat16(v - __bfloat162float(h));
    }
}

// ---------------- SIMT SGEMM (small GEMMs) ----------------
template <int BM, int BN, int BK, int TM, int TN>
__global__ __launch_bounds__(256)
void sgemm_kernel(int M, int N, int K,
                  const float* __restrict__ A,
                  const float* __restrict__ B,
                  float* __restrict__ C)
{
    __shared__ float As[BK][BM];
    __shared__ float Bs[BK][BN];
    constexpr int TCOLS = BN / TN;
    const int tid  = threadIdx.x;
    const int tCol = tid % TCOLS;
    const int tRow = tid / TCOLS;
    const int rowBase = blockIdx.y * BM;
    const int colBase = blockIdx.x * BN;

    float acc[TM][TN];
#pragma unroll
    for (int i = 0; i < TM; i++)
#pragma unroll
        for (int j = 0; j < TN; j++) acc[i][j] = 0.0f;

    for (int k0 = 0; k0 < K; k0 += BK) {
#pragma unroll
        for (int i = tid; i < BM * BK; i += 256) {
            const int r = i / BK, c = i % BK;
            const int gr = rowBase + r;
            As[c][r] = (gr < M) ? A[(size_t)gr * K + (k0 + c)] : 0.0f;
        }
#pragma unroll
        for (int i = tid; i < BK * BN; i += 256) {
            const int r = i / BN, c = i % BN;
            Bs[r][c] = B[(size_t)(k0 + r) * N + (colBase + c)];
        }
        __syncthreads();
#pragma unroll
        for (int kk = 0; kk < BK; kk++) {
            float regA[TM], regB[TN];
            const float4* a4 = reinterpret_cast<const float4*>(&As[kk][tRow * TM]);
#pragma unroll
            for (int i = 0; i < TM / 4; i++) {
                float4 v = a4[i];
                regA[4*i+0] = v.x; regA[4*i+1] = v.y; regA[4*i+2] = v.z; regA[4*i+3] = v.w;
            }
            const float4* b4 = reinterpret_cast<const float4*>(&Bs[kk][tCol * TN]);
#pragma unroll
            for (int j = 0; j < TN / 4; j++) {
                float4 v = b4[j];
                regB[4*j+0] = v.x; regB[4*j+1] = v.y; regB[4*j+2] = v.z; regB[4*j+3] = v.w;
            }
#pragma unroll
            for (int i = 0; i < TM; i++)
#pragma unroll
                for (int j = 0; j < TN; j++)
                    acc[i][j] = fmaf(regA[i], regB[j], acc[i][j]);
        }
        __syncthreads();
    }
#pragma unroll
    for (int i = 0; i < TM; i++) {
        const int gr = rowBase + tRow * TM + i;
        if (gr < M) {
#pragma unroll
            for (int j = 0; j < TN; j += 4) {
                const int gc = colBase + tCol * TN + j;
                float4 v;
                v.x = acc[i][j+0]; v.y = acc[i][j+1]; v.z = acc[i][j+2]; v.w = acc[i][j+3];
                *reinterpret_cast<float4*>(&C[(size_t)gr * N + gc]) = v;
            }
        }
    }
}

// ---------------- launcher ----------------
extern "C" void kernel_launch(void* const* d_in, const int* in_sizes, int n_in,
                              void* d_out, int out_size)
{
    const float* x   = (const float*)d_in[0];
    const float* adj = (const float*)d_in[1];
    const float* W1  = (const float*)d_in[2];
    const float* b1  = (const float*)d_in[3];
    const float* W2  = (const float*)d_in[4];
    const float* b2  = (const float*)d_in[5];
    float* out = (float*)d_out;

    float *T1, *H, *T2, *part;
    __nv_bfloat16 *Ahi, *Alo, *T1hi, *T1lo, *T2hi, *T2lo;
    cudaGetSymbolAddress((void**)&T1,  g_T1);
    cudaGetSymbolAddress((void**)&H,   g_H);
    cudaGetSymbolAddress((void**)&T2,  g_T2);
    cudaGetSymbolAddress((void**)&part, g_part);
    cudaGetSymbolAddress((void**)&Ahi, g_adj_hi);
    cudaGetSymbolAddress((void**)&Alo, g_adj_lo);
    cudaGetSymbolAddress((void**)&T1hi, g_T1t_hi);
    cudaGetSymbolAddress((void**)&T1lo, g_T1t_lo);
    cudaGetSymbolAddress((void**)&T2hi, g_T2t_hi);
    cudaGetSymbolAddress((void**)&T2lo, g_T2t_lo);

    const int TC_SMEM = 196608;   // 2 stages x 96KB
    cudaFuncSetAttribute(tc_gemm<8, 2>, cudaFuncAttributeMaxDynamicSharedMemorySize, TC_SMEM);
    cudaFuncSetAttribute(tc_gemm<4, 4>, cudaFuncAttributeMaxDynamicSharedMemorySize, TC_SMEM);

    // adj -> bf16 hi/lo (padded)
    {
        const long long total = (long long)MPAD * (KPAD / 4);
        split_adj_kernel<<<(unsigned)((total + 255) / 256), 256>>>(adj, Ahi, Alo);
    }
    // T1 = x @ W1
    sgemm_kernel<64, 128, 8, 4, 8><<<dim3(1, (NROWS + 63) / 64), 256>>>(
        NROWS, NHID, NFEAT, x, W1, T1);
    // T1t split -> [NHID, KPAD]
    tsplit_kernel<<<dim3(NHID / 32, KPAD / 32), dim3(32, 8)>>>(T1, NROWS, NHID, T1hi, T1lo);
    // gemm2 partials (256x128 tiles, K-split 4)
    tc_gemm<8, 2><<<dim3(1, MPAD / 256, 4), 512, TC_SMEM>>>(
        Ahi, Alo, T1hi, T1lo, part, NHID, (size_t)MPAD * NHID);
    // H = relu(sum parts + b1)
    reduce_kernel<4, true><<<(NROWS * (NHID / 4) + 255) / 256, 256>>>(
        part, (size_t)MPAD * NHID, b1, H, NROWS, NHID);
    // T2 = H @ W2
    sgemm_kernel<128, 128, 8, 8, 8><<<dim3(NFEAT / 128, (NROWS + 127) / 128), 256>>>(
        NROWS, NFEAT, NHID, H, W2, T2);
    // T2t split -> [NFEAT, KPAD]
    tsplit_kernel<<<dim3(NFEAT / 32, KPAD / 32), dim3(32, 8)>>>(T2, NROWS, NFEAT, T2hi, T2lo);
    // gemm4 partials (128x256 tiles, K-split 4)
    tc_gemm<4, 4><<<dim3(NFEAT / 256, 10112 / 128, 4), 512, TC_SMEM>>>(
        Ahi, Alo, T2hi, T2lo, part, NFEAT, (size_t)MPAD * NFEAT);
    // out = sum parts + b2
    reduce_kernel<4, false><<<(NROWS * (NFEAT / 4) + 255) / 256, 256>>>(
        part, (size_t)MPAD * NFEAT, b2, out, NROWS, NFEAT);
}

// round 7
// speedup vs baseline: 1.1669x; 1.1669x over previous
#include <cuda_runtime.h>
#include <cuda_bf16.h>
#include <cstdint>

// ---------------- problem constants ----------------
#define NROWS  10000
#define MPAD   10112           // 79 * 128
#define NHID   128
#define NFEAT  512
#define KPAD   10048           // 157 * 64
#define BKC    64
#define NCHUNK (KPAD / BKC)    // 157
#define TILE_B  16384u         // 128 rows * 128B (swizzled)
#define STAGE_B (4u * TILE_B)  // 65536 (Ahi, Alo, Bhi, Blo)
#define NSTAGES 3
#define TC_SMEM (NSTAGES * STAGE_B)   // 196608
#define Z2 12                  // gemm2 K-split
#define Z4 4                   // gemm4 K-split

// ---------------- scratch (__device__ globals; no allocs) ----------------
__device__ __align__(256) float g_T1[NROWS * NHID];
__device__ __align__(256) float g_H [NROWS * NHID];
__device__ __align__(256) float g_T2[NROWS * NFEAT];
__device__ __align__(256) float g_part[Z2 * (size_t)MPAD * NHID > Z4 * (size_t)MPAD * NFEAT
                                       ? Z2 * (size_t)MPAD * NHID
                                       : Z4 * (size_t)MPAD * NFEAT];
__device__ __align__(256) __nv_bfloat16 g_adj_hi[(size_t)MPAD * KPAD];
__device__ __align__(256) __nv_bfloat16 g_adj_lo[(size_t)MPAD * KPAD];
__device__ __align__(256) __nv_bfloat16 g_T1t_hi[NHID * KPAD];
__device__ __align__(256) __nv_bfloat16 g_T1t_lo[NHID * KPAD];
__device__ __align__(256) __nv_bfloat16 g_T2t_hi[NFEAT * KPAD];
__device__ __align__(256) __nv_bfloat16 g_T2t_lo[NFEAT * KPAD];

// ---------------- PTX helpers (legal on bare sm_103) ----------------
__device__ __forceinline__ uint32_t smem_u32(const void* p) {
    uint32_t a;
    asm("{ .reg .u64 t; cvta.to.shared.u64 t, %1; cvt.u32.u64 %0, t; }" : "=r"(a) : "l"(p));
    return a;
}
__device__ __forceinline__ uint32_t swz(uint32_t off) {
    return off ^ ((off >> 3) & 0x70);
}
__device__ __forceinline__ void cp_async16(uint32_t dst, const void* src) {
    asm volatile("cp.async.cg.shared.global [%0], [%1], 16;" :: "r"(dst), "l"(src));
}
__device__ __forceinline__ void cp_commit() {
    asm volatile("cp.async.commit_group;" ::: "memory");
}
template <int N>
__device__ __forceinline__ void cp_wait() {
    asm volatile("cp.async.wait_group %0;" :: "n"(N) : "memory");
}
__device__ __forceinline__ void ldsm4(uint32_t* r, uint32_t addr) {
    asm volatile("ldmatrix.sync.aligned.m8n8.x4.shared.b16 {%0,%1,%2,%3}, [%4];"
                 : "=r"(r[0]), "=r"(r[1]), "=r"(r[2]), "=r"(r[3]) : "r"(addr));
}
__device__ __forceinline__ void mma_bf16(float* d, const uint32_t* a,
                                         uint32_t b0, uint32_t b1) {
    asm volatile(
        "mma.sync.aligned.m16n8k16.row.col.f32.bf16.bf16.f32 "
        "{%0,%1,%2,%3}, {%4,%5,%6,%7}, {%8,%9}, {%0,%1,%2,%3};"
        : "+f"(d[0]), "+f"(d[1]), "+f"(d[2]), "+f"(d[3])
        : "r"(a[0]), "r"(a[1]), "r"(a[2]), "r"(a[3]), "r"(b0), "r"(b1));
}

// ---------------- HMMA split-bf16 GEMM (partial sums) ----------------
// part[z][m][n] = sum_{k in range z} (Ahi+Alo)[m][k]*(Bhi+Blo)[n][k]  (3 products)
// A: [MPAD, KPAD] bf16 K-major; B: [Ntot, KPAD] bf16 K-major.
__global__ __launch_bounds__(512, 1)
void tc_gemm(const __nv_bfloat16* __restrict__ Ahi,
             const __nv_bfloat16* __restrict__ Alo,
             const __nv_bfloat16* __restrict__ Bhi,
             const __nv_bfloat16* __restrict__ Blo,
             float* __restrict__ C, int ldC, size_t part_stride)
{
    extern __shared__ __align__(128) char smem[];
    const uint32_t sbase = smem_u32(smem);
    const int tid  = threadIdx.x;
    const int wid  = tid >> 5;
    const int lane = tid & 31;
    const int wm = wid & 3;            // 4 warp-rows of 32
    const int wn = wid >> 2;           // 4 warp-cols of 32
    const int m0 = blockIdx.y * 128;
    const int n0 = blockIdx.x * 128;

    const int gz = gridDim.z, bz = blockIdx.z;
    const int cbeg = (NCHUNK * bz) / gz;
    const int cend = (NCHUNK * (bz + 1)) / gz;
    C += (size_t)bz * part_stride;

    const char* bases[4] = {
        (const char*)(Ahi + (size_t)m0 * KPAD),
        (const char*)(Alo + (size_t)m0 * KPAD),
        (const char*)(Bhi + (size_t)n0 * KPAD),
        (const char*)(Blo + (size_t)n0 * KPAD)
    };

    auto load_stage = [&](int c) {
        const uint32_t st = sbase + (uint32_t)(c % NSTAGES) * STAGE_B;
        const size_t kb = (size_t)c * (BKC * 2);
#pragma unroll
        for (int i = 0; i < 8; i++) {
            const int idx = tid + i * 512;          // 0..4095
            const int t   = idx >> 10;              // tile 0..3
            const int rem = idx & 1023;
            const int r   = rem >> 3;               // row 0..127
            const int cc  = rem & 7;                // 16B chunk
            cp_async16(st + (uint32_t)t * TILE_B + swz((uint32_t)(r * 128 + cc * 16)),
                       bases[t] + kb + (size_t)r * (KPAD * 2) + cc * 16);
        }
        cp_commit();
    };

    // ldmatrix logical offsets (swizzle applied per-use)
    const uint32_t rL   = lane & 15;
    const uint32_t cAdd = lane >> 4;
    const uint32_t aRow0 = (uint32_t)(wm * 32 + rL);
    const uint32_t bRow0 = (uint32_t)(wn * 32 + rL);
    const uint32_t kOff0 = cAdd * 16u;

    float acc[2][4][4];
#pragma unroll
    for (int i = 0; i < 2; i++)
#pragma unroll
        for (int j = 0; j < 4; j++)
#pragma unroll
            for (int k = 0; k < 4; k++) acc[i][j][k] = 0.0f;

    // prologue
    load_stage(cbeg);
    if (cbeg + 1 < cend) load_stage(cbeg + 1);

    for (int c = cbeg; c < cend; c++) {
        if (c + 1 < cend) cp_wait<1>(); else cp_wait<0>();
        __syncthreads();
        if (c + 2 < cend) load_stage(c + 2);   // overlaps with compute below

        const uint32_t st   = sbase + (uint32_t)(c % NSTAGES) * STAGE_B;
        const uint32_t tAhi = st;
        const uint32_t tAlo = st + TILE_B;
        const uint32_t tBhi = st + 2u * TILE_B;
        const uint32_t tBlo = st + 3u * TILE_B;

#pragma unroll
        for (int ks = 0; ks < 4; ks++) {
            const uint32_t kb = kOff0 + (uint32_t)ks * 32u;
            uint32_t Ah[2][4], Al[2][4], Bh[2][4], Bl[2][4];
#pragma unroll
            for (int mt = 0; mt < 2; mt++) {
                const uint32_t off = (aRow0 + mt * 16u) * 128u + kb;
                ldsm4(Ah[mt], tAhi + swz(off));
                ldsm4(Al[mt], tAlo + swz(off));
            }
#pragma unroll
            for (int nh = 0; nh < 2; nh++) {
                const uint32_t off = (bRow0 + nh * 16u) * 128u + kb;
                ldsm4(Bh[nh], tBhi + swz(off));
                ldsm4(Bl[nh], tBlo + swz(off));
            }
#pragma unroll
            for (int mt = 0; mt < 2; mt++) {
                // hi*hi
                mma_bf16(acc[mt][0], Ah[mt], Bh[0][0], Bh[0][2]);
                mma_bf16(acc[mt][1], Ah[mt], Bh[0][1], Bh[0][3]);
                mma_bf16(acc[mt][2], Ah[mt], Bh[1][0], Bh[1][2]);
                mma_bf16(acc[mt][3], Ah[mt], Bh[1][1], Bh[1][3]);
                // hi*lo
                mma_bf16(acc[mt][0], Ah[mt], Bl[0][0], Bl[0][2]);
                mma_bf16(acc[mt][1], Ah[mt], Bl[0][1], Bl[0][3]);
                mma_bf16(acc[mt][2], Ah[mt], Bl[1][0], Bl[1][2]);
                mma_bf16(acc[mt][3], Ah[mt], Bl[1][1], Bl[1][3]);
                // lo*hi
                mma_bf16(acc[mt][0], Al[mt], Bh[0][0], Bh[0][2]);
                mma_bf16(acc[mt][1], Al[mt], Bh[0][1], Bh[0][3]);
                mma_bf16(acc[mt][2], Al[mt], Bh[1][0], Bh[1][2]);
                mma_bf16(acc[mt][3], Al[mt], Bh[1][1], Bh[1][3]);
            }
        }
    }

    // ---- epilogue: raw partial sums ----
    const int trow  = lane >> 2;
    const int tcol2 = (lane & 3) * 2;
#pragma unroll
    for (int mt = 0; mt < 2; mt++) {
#pragma unroll
        for (int h = 0; h < 2; h++) {
            const int gr = m0 + wm * 32 + mt * 16 + h * 8 + trow;
#pragma unroll
            for (int nf = 0; nf < 4; nf++) {
                const int gc = n0 + wn * 32 + nf * 8 + tcol2;
                float2 v;
                v.x = acc[mt][nf][h * 2 + 0];
                v.y = acc[mt][nf][h * 2 + 1];
                *reinterpret_cast<float2*>(&C[(size_t)gr * ldC + gc]) = v;
            }
        }
    }
}

// ---------------- split-K reduce: out = (sum parts) + bias (, relu) ----------------
template <int NP, bool RELU>
__global__ void reduce_kernel(const float* __restrict__ part, size_t stride,
                              const float* __restrict__ bias,
                              float* __restrict__ out, int rows, int cols)
{
    const int t = blockIdx.x * blockDim.x + threadIdx.x;
    if (t >= rows * (cols / 4)) return;
    const int r = t / (cols / 4);
    const int c = (t % (cols / 4)) * 4;
    float4 s = *reinterpret_cast<const float4*>(bias + c);
#pragma unroll
    for (int p = 0; p < NP; p++) {
        const float4 v = *reinterpret_cast<const float4*>(part + p * stride + (size_t)r * cols + c);
        s.x += v.x; s.y += v.y; s.z += v.z; s.w += v.w;
    }
    if (RELU) {
        s.x = fmaxf(s.x, 0.0f); s.y = fmaxf(s.y, 0.0f);
        s.z = fmaxf(s.z, 0.0f); s.w = fmaxf(s.w, 0.0f);
    }
    *reinterpret_cast<float4*>(out + (size_t)r * cols + c) = s;
}

// ---------------- adj split: fp32 -> bf16 hi/lo [MPAD,KPAD] ----------------
__global__ void split_adj_kernel(const float* __restrict__ adj,
                                 __nv_bfloat16* __restrict__ hi,
                                 __nv_bfloat16* __restrict__ lo)
{
    const long long t = (long long)blockIdx.x * blockDim.x + threadIdx.x;
    const long long total = (long long)MPAD * (KPAD / 4);
    if (t >= total) return;
    const int c4 = (int)(t % (KPAD / 4));
    const int r  = (int)(t / (KPAD / 4));
    const int k  = c4 * 4;
    float4 v = make_float4(0.f, 0.f, 0.f, 0.f);
    if (r < NROWS && k < NROWS)
        v = *reinterpret_cast<const float4*>(adj + (size_t)r * NROWS + k);
    __nv_bfloat16 h0 = __float2bfloat16(v.x), h1 = __float2bfloat16(v.y);
    __nv_bfloat16 h2 = __float2bfloat16(v.z), h3 = __float2bfloat16(v.w);
    __nv_bfloat16 l0 = __float2bfloat16(v.x - __bfloat162float(h0));
    __nv_bfloat16 l1 = __float2bfloat16(v.y - __bfloat162float(h1));
    __nv_bfloat16 l2 = __float2bfloat16(v.z - __bfloat162float(h2));
    __nv_bfloat16 l3 = __float2bfloat16(v.w - __bfloat162float(h3));
    __nv_bfloat162 H01, H23, L01, L23;
    H01.x = h0; H01.y = h1; H23.x = h2; H23.y = h3;
    L01.x = l0; L01.y = l1; L23.x = l2; L23.y = l3;
    __nv_bfloat162* hp = reinterpret_cast<__nv_bfloat162*>(hi + (size_t)r * KPAD + k);
    __nv_bfloat162* lp = reinterpret_cast<__nv_bfloat162*>(lo + (size_t)r * KPAD + k);
    hp[0] = H01; hp[1] = H23;
    lp[0] = L01; lp[1] = L23;
}

// -------- tiled transpose + split: fp32 [R,C] -> bf16 hi/lo [C, KPAD] --------
// grid (C/32, KPAD/32), block (32, 8). Coalesced on both sides.
__global__ void tsplit_kernel(const float* __restrict__ in, int R, int C,
                              __nv_bfloat16* __restrict__ hi,
                              __nv_bfloat16* __restrict__ lo)
{
    __shared__ float tile[32][33];
    const int tx = threadIdx.x, ty = threadIdx.y;
    const int c0 = blockIdx.x * 32;
    const int k0 = blockIdx.y * 32;
#pragma unroll
    for (int i = 0; i < 4; i++) {
        const int k = k0 + ty + i * 8;
        tile[ty + i * 8][tx] = (k < R) ? in[(size_t)k * C + (c0 + tx)] : 0.0f;
    }
    __syncthreads();
#pragma unroll
    for (int i = 0; i < 4; i++) {
        const int c = c0 + ty + i * 8;
        const float v = tile[tx][ty + i * 8];
        const __nv_bfloat16 h = __float2bfloat16(v);
        hi[(size_t)c * KPAD + k0 + tx] = h;
        lo[(size_t)c * KPAD + k0 + tx] = __float2bfloat16(v - __bfloat162float(h));
    }
}

// ---------------- SIMT SGEMM (small GEMMs) ----------------
template <int BM, int BN, int BK, int TM, int TN>
__global__ __launch_bounds__(256)
void sgemm_kernel(int M, int N, int K,
                  const float* __restrict__ A,
                  const float* __restrict__ B,
                  float* __restrict__ C)
{
    __shared__ float As[BK][BM];
    __shared__ float Bs[BK][BN];
    constexpr int TCOLS = BN / TN;
    const int tid  = threadIdx.x;
    const int tCol = tid % TCOLS;
    const int tRow = tid / TCOLS;
    const int rowBase = blockIdx.y * BM;
    const int colBase = blockIdx.x * BN;

    float acc[TM][TN];
#pragma unroll
    for (int i = 0; i < TM; i++)
#pragma unroll
        for (int j = 0; j < TN; j++) acc[i][j] = 0.0f;

    for (int k0 = 0; k0 < K; k0 += BK) {
#pragma unroll
        for (int i = tid; i < BM * BK; i += 256) {
            const int r = i / BK, c = i % BK;
            const int gr = rowBase + r;
            As[c][r] = (gr < M) ? A[(size_t)gr * K + (k0 + c)] : 0.0f;
        }
#pragma unroll
        for (int i = tid; i < BK * BN; i += 256) {
            const int r = i / BN, c = i % BN;
            Bs[r][c] = B[(size_t)(k0 + r) * N + (colBase + c)];
        }
        __syncthreads();
#pragma unroll
        for (int kk = 0; kk < BK; kk++) {
            float regA[TM], regB[TN];
            const float4* a4 = reinterpret_cast<const float4*>(&As[kk][tRow * TM]);
#pragma unroll
            for (int i = 0; i < TM / 4; i++) {
                float4 v = a4[i];
                regA[4*i+0] = v.x; regA[4*i+1] = v.y; regA[4*i+2] = v.z; regA[4*i+3] = v.w;
            }
            const float4* b4 = reinterpret_cast<const float4*>(&Bs[kk][tCol * TN]);
#pragma unroll
            for (int j = 0; j < TN / 4; j++) {
                float4 v = b4[j];
                regB[4*j+0] = v.x; regB[4*j+1] = v.y; regB[4*j+2] = v.z; regB[4*j+3] = v.w;
            }
#pragma unroll
            for (int i = 0; i < TM; i++)
#pragma unroll
                for (int j = 0; j < TN; j++)
                    acc[i][j] = fmaf(regA[i], regB[j], acc[i][j]);
        }
        __syncthreads();
    }
#pragma unroll
    for (int i = 0; i < TM; i++) {
        const int gr = rowBase + tRow * TM + i;
        if (gr < M) {
#pragma unroll
            for (int j = 0; j < TN; j += 4) {
                const int gc = colBase + tCol * TN + j;
                float4 v;
                v.x = acc[i][j+0]; v.y = acc[i][j+1]; v.z = acc[i][j+2]; v.w = acc[i][j+3];
                *reinterpret_cast<float4*>(&C[(size_t)gr * N + gc]) = v;
            }
        }
    }
}

// ---------------- launcher ----------------
extern "C" void kernel_launch(void* const* d_in, const int* in_sizes, int n_in,
                              void* d_out, int out_size)
{
    const float* x   = (const float*)d_in[0];
    const float* adj = (const float*)d_in[1];
    const float* W1  = (const float*)d_in[2];
    const float* b1  = (const float*)d_in[3];
    const float* W2  = (const float*)d_in[4];
    const float* b2  = (const float*)d_in[5];
    float* out = (float*)d_out;

    float *T1, *H, *T2, *part;
    __nv_bfloat16 *Ahi, *Alo, *T1hi, *T1lo, *T2hi, *T2lo;
    cudaGetSymbolAddress((void**)&T1,  g_T1);
    cudaGetSymbolAddress((void**)&H,   g_H);
    cudaGetSymbolAddress((void**)&T2,  g_T2);
    cudaGetSymbolAddress((void**)&part, g_part);
    cudaGetSymbolAddress((void**)&Ahi, g_adj_hi);
    cudaGetSymbolAddress((void**)&Alo, g_adj_lo);
    cudaGetSymbolAddress((void**)&T1hi, g_T1t_hi);
    cudaGetSymbolAddress((void**)&T1lo, g_T1t_lo);
    cudaGetSymbolAddress((void**)&T2hi, g_T2t_hi);
    cudaGetSymbolAddress((void**)&T2lo, g_T2t_lo);

    cudaFuncSetAttribute(tc_gemm, cudaFuncAttributeMaxDynamicSharedMemorySize, TC_SMEM);

    // adj -> bf16 hi/lo (padded)
    {
        const long long total = (long long)MPAD * (KPAD / 4);
        split_adj_kernel<<<(unsigned)((total + 255) / 256), 256>>>(adj, Ahi, Alo);
    }
    // T1 = x @ W1
    sgemm_kernel<64, 128, 8, 4, 8><<<dim3(1, (NROWS + 63) / 64), 256>>>(
        NROWS, NHID, NFEAT, x, W1, T1);
    // T1t split -> [NHID, KPAD] (coalesced tiled transpose)
    tsplit_kernel<<<dim3(NHID / 32, KPAD / 32), dim3(32, 8)>>>(T1, NROWS, NHID, T1hi, T1lo);
    // gemm2 partials (K-split Z2)
    tc_gemm<<<dim3(1, MPAD / 128, Z2), 512, TC_SMEM>>>(
        Ahi, Alo, T1hi, T1lo, part, NHID, (size_t)MPAD * NHID);
    // H = relu(sum parts + b1)
    reduce_kernel<Z2, true><<<(NROWS * (NHID / 4) + 255) / 256, 256>>>(
        part, (size_t)MPAD * NHID, b1, H, NROWS, NHID);
    // T2 = H @ W2
    sgemm_kernel<128, 128, 8, 8, 8><<<dim3(NFEAT / 128, (NROWS + 127) / 128), 256>>>(
        NROWS, NFEAT, NHID, H, W2, T2);
    // T2t split -> [NFEAT, KPAD] (coalesced tiled transpose)
    tsplit_kernel<<<dim3(NFEAT / 32, KPAD / 32), dim3(32, 8)>>>(T2, NROWS, NFEAT, T2hi, T2lo);
    // gemm4 partials (K-split Z4)
    tc_gemm<<<dim3(NFEAT / 128, MPAD / 128, Z4), 512, TC_SMEM>>>(
        Ahi, Alo, T2hi, T2lo, part, NFEAT, (size_t)MPAD * NFEAT);
    // out = sum parts + b2
    reduce_kernel<Z4, false><<<(NROWS * (NFEAT / 4) + 255) / 256, 256>>>(
        part, (size_t)MPAD * NFEAT, b2, out, NROWS, NFEAT);
}